// round 1
// baseline (speedup 1.0000x reference)
#include <cuda_runtime.h>
#include <math.h>

#define BATCH   128
#define M_NODES 64
#define SEQROWS (BATCH * M_NODES)   // 8192
#define LATENT  256
#define HIDDEN  512
#define G3      1536
#define NPAIR   2016

// ---------------- scratch (static device allocations; no cudaMalloc) ----------------
__device__ float g_x   [SEQROWS * 512];     // concat(z+pe, emb) rows, time-major (r = t*128+b)
__device__ float g_seq [SEQROWS * LATENT];  // pre-projected + masked sequence
__device__ float g_gi  [SEQROWS * G3];      // input-gate preactivations (reused layer0 then layer1)
__device__ float g_hs0 [SEQROWS * HIDDEN];  // layer0 outputs (time-major)
__device__ float g_hs1 [SEQROWS * HIDDEN];  // layer1 outputs (time-major)
__device__ float g_node[SEQROWS * HIDDEN];  // node embeddings
__device__ float g_ca  [SEQROWS * HIDDEN];  // per-node contribution via adj_W1[:, :512]
__device__ float g_cb  [SEQROWS * HIDDEN];  // per-node contribution via adj_W1[:, 512:]
__device__ float g_h   [2][BATCH * HIDDEN]; // GRU hidden ping-pong

// ---------------- helpers ----------------
__device__ __forceinline__ float sigm(float x) {
    // jax.nn.sigmoid == logistic == 0.5*(tanh(x/2)+1)
    return 0.5f * tanhf(0.5f * x) + 0.5f;
}

// ---------------- build x = concat(z[b]+pe[t], emb[t]), time-major rows ----------------
__global__ void build_x(const float* __restrict__ z, const float* __restrict__ pe,
                        const float* __restrict__ emb, float* __restrict__ x)
{
    int idx = blockIdx.x * blockDim.x + threadIdx.x;   // total 8192*512, grid exact
    int c = idx & 511;
    int r = idx >> 9;
    int b = r & 127;
    int t = r >> 7;
    float v;
    if (c < 256) v = z[b * 256 + c] + pe[t * 256 + c];
    else         v = emb[t * 256 + (c - 256)];
    x[idx] = v;
}

// ---------------- masking: zero rows with t >= n_nodes[b] ----------------
__global__ void mask_kernel(float* __restrict__ buf, const int* __restrict__ n_nodes,
                            int logw)
{
    int idx = blockIdx.x * blockDim.x + threadIdx.x;   // grid sized exactly
    int r = idx >> logw;
    int b = r & 127;
    int t = r >> 7;
    if (t >= n_nodes[b]) buf[idx] = 0.0f;
}

// ---------------- generic SGEMM: C[M][N] = A[M][K] @ B[N][K]^T (+bias[N]) ----------------
// Requirements (all satisfied by our shapes): M%64==0, N%64==0, K%16==0.
__global__ __launch_bounds__(256)
void sgemm(const float* __restrict__ A, int lda,
           const float* __restrict__ B, int ldb,
           float* __restrict__ C, int ldc,
           const float* __restrict__ bias, int K)
{
    __shared__ float As[16][68];
    __shared__ float Bs[16][68];
    const int tid = threadIdx.x;
    const int tx  = tid & 15;
    const int ty  = tid >> 4;
    const int m0  = blockIdx.y * 64;
    const int n0  = blockIdx.x * 64;
    const int lrow = tid >> 2;          // 0..63
    const int lk4  = (tid & 3) << 2;    // 0,4,8,12
    const float* Ap = A + (long)(m0 + lrow) * lda + lk4;
    const float* Bp = B + (long)(n0 + lrow) * ldb + lk4;

    float acc[4][4] = {};
    for (int k0 = 0; k0 < K; k0 += 16) {
        float4 av = *(const float4*)(Ap + k0);
        float4 bv = *(const float4*)(Bp + k0);
        __syncthreads();
        As[lk4+0][lrow] = av.x; As[lk4+1][lrow] = av.y;
        As[lk4+2][lrow] = av.z; As[lk4+3][lrow] = av.w;
        Bs[lk4+0][lrow] = bv.x; Bs[lk4+1][lrow] = bv.y;
        Bs[lk4+2][lrow] = bv.z; Bs[lk4+3][lrow] = bv.w;
        __syncthreads();
        #pragma unroll
        for (int kk = 0; kk < 16; kk++) {
            float4 a = *(const float4*)&As[kk][ty << 2];
            float4 b = *(const float4*)&Bs[kk][tx << 2];
            float ar[4] = {a.x, a.y, a.z, a.w};
            float br[4] = {b.x, b.y, b.z, b.w};
            #pragma unroll
            for (int i = 0; i < 4; i++)
                #pragma unroll
                for (int j = 0; j < 4; j++)
                    acc[i][j] = fmaf(ar[i], br[j], acc[i][j]);
        }
    }
    #pragma unroll
    for (int j = 0; j < 4; j++) {
        int n = n0 + (tx << 2) + j;
        float bj = bias ? bias[n] : 0.0f;
        #pragma unroll
        for (int i = 0; i < 4; i++)
            C[(long)(m0 + (ty << 2) + i) * ldc + n] = acc[i][j] + bj;
    }
}

// ---------------- fused GRU step: gh = h@Whh^T + bhh; gates; h_new ----------------
// grid (16, 8): blockIdx.x -> 32 hidden cols, blockIdx.y -> 16 batches. 128 threads.
__global__ __launch_bounds__(128)
void gru_step(const float* __restrict__ gi,     // [128][1536] this timestep
              const float* __restrict__ h_in,   // [128][512]
              const float* __restrict__ Whh,    // [1536][512]
              const float* __restrict__ bhh,    // [1536]
              float* __restrict__ h_out,        // [128][512]
              float* __restrict__ seq_out)      // [128][512] (slice of layer output)
{
    __shared__ float h_s[16][HIDDEN];        // 32 KB
    __shared__ float w_s[3][32][36];         // 13.5 KB (padded: conflict-free)
    const int tid  = threadIdx.x;
    const int lane = tid & 31;               // j within tile
    const int trow = tid >> 5;               // 0..3, batch interleave
    const int j0 = blockIdx.x * 32;
    const int b0 = blockIdx.y * 16;

    #pragma unroll
    for (int it = 0; it < 16; it++) {
        int f4  = tid + 128 * it;            // 0..2047 float4s
        int row = f4 >> 7;
        int c4  = (f4 & 127) << 2;
        *(float4*)&h_s[row][c4] = *(const float4*)&h_in[(b0 + row) * HIDDEN + c4];
    }

    float accR[4] = {}, accZ[4] = {}, accN[4] = {};
    for (int kt = 0; kt < 16; kt++) {
        __syncthreads();
        #pragma unroll
        for (int it = 0; it < 6; it++) {
            int l   = tid + 128 * it;        // < 768 float4s
            int row = l >> 3;                // 0..95
            int c4  = (l & 7) << 2;
            int gg  = row >> 5, jj = row & 31;
            *(float4*)&w_s[gg][jj][c4] =
                *(const float4*)&Whh[(gg * HIDDEN + j0 + jj) * HIDDEN + kt * 32 + c4];
        }
        __syncthreads();
        #pragma unroll
        for (int kk = 0; kk < 32; kk += 4) {
            float4 wr = *(const float4*)&w_s[0][lane][kk];
            float4 wz = *(const float4*)&w_s[1][lane][kk];
            float4 wn = *(const float4*)&w_s[2][lane][kk];
            #pragma unroll
            for (int bb = 0; bb < 4; bb++) {
                int lb = trow + (bb << 2);
                float4 hv = *(const float4*)&h_s[lb][kt * 32 + kk];
                accR[bb] += wr.x*hv.x + wr.y*hv.y + wr.z*hv.z + wr.w*hv.w;
                accZ[bb] += wz.x*hv.x + wz.y*hv.y + wz.z*hv.z + wz.w*hv.w;
                accN[bb] += wn.x*hv.x + wn.y*hv.y + wn.z*hv.z + wn.w*hv.w;
            }
        }
    }

    const int j = j0 + lane;
    const float br = bhh[j], bz = bhh[HIDDEN + j], bn = bhh[2 * HIDDEN + j];
    #pragma unroll
    for (int bb = 0; bb < 4; bb++) {
        int lb = trow + (bb << 2);
        int gb = b0 + lb;
        const float* grow = gi + gb * G3;
        float r    = sigm(grow[j]              + accR[bb] + br);
        float zg   = sigm(grow[HIDDEN + j]     + accZ[bb] + bz);
        float n    = tanhf(grow[2 * HIDDEN + j] + r * (accN[bb] + bn));
        float hold = h_s[lb][j];
        float hnew = (1.0f - zg) * n + zg * hold;
        h_out[gb * HIDDEN + j]  = hnew;
        seq_out[gb * HIDDEN + j] = hnew;
    }
}

// ---------------- pair kernel: one warp per (b, pair) ----------------
__global__ __launch_bounds__(256)
void pair_kernel(const float* __restrict__ ca, const float* __restrict__ cb,
                 const float* __restrict__ b1, const float* __restrict__ W2,
                 const float* __restrict__ b2, const float* __restrict__ gu,
                 const int* __restrict__ n_nodes, float* __restrict__ out)
{
    int w    = (blockIdx.x * blockDim.x + threadIdx.x) >> 5;
    int lane = threadIdx.x & 31;
    // w < 128*2016 exactly by grid sizing
    int b = w / NPAIR;
    int p = w - b * NPAIR;
    int i = 0, rem = p, len = 63;
    while (rem >= len) { rem -= len; len--; i++; }
    int j = i + 1 + rem;

    const float* ra = ca + (long)(i * 128 + b) * HIDDEN;
    const float* rb = cb + (long)(j * 128 + b) * HIDDEN;
    float a0 = 0.0f, a1 = 0.0f;
    #pragma unroll
    for (int kk = 0; kk < 16; kk++) {
        int idx = (kk << 5) + lane;
        float v = ra[idx] + rb[idx] + b1[idx];
        v = fmaxf(v, 0.0f);
        a0 = fmaf(v, W2[idx], a0);
        a1 = fmaf(v, W2[HIDDEN + idx], a1);
    }
    #pragma unroll
    for (int off = 16; off; off >>= 1) {
        a0 += __shfl_down_sync(0xffffffffu, a0, off);
        a1 += __shfl_down_sync(0xffffffffu, a1, off);
    }
    if (lane == 0) {
        int n = n_nodes[b];
        if (i < n && j < n) {
            const float* g = gu + ((long)b * NPAIR + p) * 2;
            float g0 = -logf(-logf(g[0] + 1e-10f) + 1e-10f);
            float g1 = -logf(-logf(g[1] + 1e-10f) + 1e-10f);
            float s0 = a0 + b2[0] + g0;   // tau = 1
            float s1 = a1 + b2[1] + g1;
            float val = (s0 >= s1) ? 1.0f : 0.0f;   // argmax ties -> index 0
            out[((long)b * 64 + i) * 64 + j] = val;
            out[((long)b * 64 + j) * 64 + i] = val;
        }
    }
}

// ---------------- launcher ----------------
extern "C" void kernel_launch(void* const* d_in, const int* in_sizes, int n_in,
                              void* d_out, int out_size)
{
    (void)in_sizes; (void)n_in;
    const float* z       = (const float*)d_in[0];
    const int*   n_nodes = (const int*)  d_in[1];
    // d_in[2] = n_edges (unused)
    const float* gu      = (const float*)d_in[3];
    const float* emb     = (const float*)d_in[4];
    const float* pe      = (const float*)d_in[5];
    const float* W_pre   = (const float*)d_in[6];
    const float* b_pre   = (const float*)d_in[7];
    const float* Wih0    = (const float*)d_in[8];
    const float* Whh0    = (const float*)d_in[9];
    const float* bih0    = (const float*)d_in[10];
    const float* bhh0    = (const float*)d_in[11];
    const float* Wih1    = (const float*)d_in[12];
    const float* Whh1    = (const float*)d_in[13];
    const float* bih1    = (const float*)d_in[14];
    const float* bhh1    = (const float*)d_in[15];
    const float* node_W  = (const float*)d_in[16];
    const float* adj_W1  = (const float*)d_in[17];
    const float* adj_b1  = (const float*)d_in[18];
    const float* adj_W2  = (const float*)d_in[19];
    const float* adj_b2  = (const float*)d_in[20];

    float *x, *seq, *gi, *hs0, *hs1, *node, *ca, *cb, *hbuf;
    cudaGetSymbolAddress((void**)&x,    g_x);
    cudaGetSymbolAddress((void**)&seq,  g_seq);
    cudaGetSymbolAddress((void**)&gi,   g_gi);
    cudaGetSymbolAddress((void**)&hs0,  g_hs0);
    cudaGetSymbolAddress((void**)&hs1,  g_hs1);
    cudaGetSymbolAddress((void**)&node, g_node);
    cudaGetSymbolAddress((void**)&ca,   g_ca);
    cudaGetSymbolAddress((void**)&cb,   g_cb);
    cudaGetSymbolAddress((void**)&hbuf, g_h);
    float* h0 = hbuf;
    float* h1 = hbuf + BATCH * HIDDEN;

    // 1) x = concat(z+pe, emb)
    build_x<<<SEQROWS * 512 / 256, 256>>>(z, pe, emb, x);
    // 2) seq = x @ W_pre^T + b_pre ; mask
    sgemm<<<dim3(LATENT / 64, SEQROWS / 64), 256>>>(x, 512, W_pre, 512, seq, LATENT, b_pre, 512);
    mask_kernel<<<SEQROWS * LATENT / 256, 256>>>(seq, n_nodes, 8);
    // 3) gi0 = seq @ Wih0^T + bih0
    sgemm<<<dim3(G3 / 64, SEQROWS / 64), 256>>>(seq, LATENT, Wih0, LATENT, gi, G3, bih0, LATENT);
    // 4) GRU layer 0 recurrence
    cudaMemsetAsync(h0, 0, BATCH * HIDDEN * sizeof(float));
    for (int t = 0; t < M_NODES; t++) {
        float* hin  = (t & 1) ? h1 : h0;
        float* hout = (t & 1) ? h0 : h1;
        gru_step<<<dim3(16, 8), 128>>>(gi + (long)t * BATCH * G3, hin, Whh0, bhh0,
                                       hout, hs0 + (long)t * BATCH * HIDDEN);
    }
    // 5) gi1 = hs0 @ Wih1^T + bih1
    sgemm<<<dim3(G3 / 64, SEQROWS / 64), 256>>>(hs0, HIDDEN, Wih1, HIDDEN, gi, G3, bih1, HIDDEN);
    // 6) GRU layer 1 recurrence
    cudaMemsetAsync(h0, 0, BATCH * HIDDEN * sizeof(float));
    for (int t = 0; t < M_NODES; t++) {
        float* hin  = (t & 1) ? h1 : h0;
        float* hout = (t & 1) ? h0 : h1;
        gru_step<<<dim3(16, 8), 128>>>(gi + (long)t * BATCH * G3, hin, Whh1, bhh1,
                                       hout, hs1 + (long)t * BATCH * HIDDEN);
    }
    // 7) mask rnn_out; node_emb = rnn_out @ node_W^T
    mask_kernel<<<SEQROWS * HIDDEN / 256, 256>>>(hs1, n_nodes, 9);
    sgemm<<<dim3(HIDDEN / 64, SEQROWS / 64), 256>>>(hs1, HIDDEN, node_W, HIDDEN, node, HIDDEN, nullptr, HIDDEN);
    // 8) per-node pair contributions through adj_W1 halves
    sgemm<<<dim3(HIDDEN / 64, SEQROWS / 64), 256>>>(node, HIDDEN, adj_W1, 1024, ca, HIDDEN, nullptr, HIDDEN);
    sgemm<<<dim3(HIDDEN / 64, SEQROWS / 64), 256>>>(node, HIDDEN, adj_W1 + 512, 1024, cb, HIDDEN, nullptr, HIDDEN);
    // 9) adjacency
    cudaMemsetAsync(d_out, 0, (size_t)out_size * sizeof(float));
    pair_kernel<<<(BATCH * NPAIR * 32) / 256, 256>>>(ca, cb, adj_b1, adj_W2, adj_b2,
                                                     gu, n_nodes, (float*)d_out);
}

// round 3
// speedup vs baseline: 1.2373x; 1.2373x over previous
#include <cuda_runtime.h>
#include <math.h>

#define BATCH   128
#define M_NODES 64
#define SEQROWS (BATCH * M_NODES)   // 8192
#define LATENT  256
#define HIDDEN  512
#define G3      1536
#define NPAIR   2016

typedef unsigned long long ull;

// ---------------- scratch ----------------
__device__ float g_x   [SEQROWS * 512];
__device__ float g_seq [SEQROWS * LATENT];
__device__ float g_gi  [SEQROWS * G3];
__device__ float g_hs0 [SEQROWS * HIDDEN];
__device__ float g_hs1 [SEQROWS * HIDDEN];
__device__ float g_node[SEQROWS * HIDDEN];
__device__ float g_ca  [SEQROWS * HIDDEN];
__device__ float g_cb  [SEQROWS * HIDDEN];
__device__ float g_h   [2][BATCH * HIDDEN];
__device__ int   g_ctr [8];

// ---------------- helpers ----------------
__device__ __forceinline__ float sigm(float x) {
    return 0.5f * tanhf(0.5f * x) + 0.5f;
}
__device__ __forceinline__ ull ffma2(ull a, ull b, ull c) {
    ull d;
    asm("fma.rn.f32x2 %0, %1, %2, %3;" : "=l"(d) : "l"(a), "l"(b), "l"(c));
    return d;
}
__device__ __forceinline__ ull dup2(float x) {
    ull r;
    asm("mov.b64 %0, {%1, %1};" : "=l"(r) : "f"(x));
    return r;
}
__device__ __forceinline__ void unpack2(ull v, float& lo, float& hi) {
    asm("mov.b64 {%0, %1}, %2;" : "=f"(lo), "=f"(hi) : "l"(v));
}

// ---------------- build x = concat(z+pe, emb), time-major rows ----------------
__global__ void build_x(const float* __restrict__ z, const float* __restrict__ pe,
                        const float* __restrict__ emb, float* __restrict__ x)
{
    int idx = blockIdx.x * blockDim.x + threadIdx.x;
    int c = idx & 511;
    int r = idx >> 9;
    int b = r & 127;
    int t = r >> 7;
    float v;
    if (c < 256) v = z[b * 256 + c] + pe[t * 256 + c];
    else         v = emb[t * 256 + (c - 256)];
    x[idx] = v;
}

// ---------------- masking ----------------
__global__ void mask_kernel(float* __restrict__ buf, const int* __restrict__ n_nodes,
                            int logw)
{
    int idx = blockIdx.x * blockDim.x + threadIdx.x;
    int r = idx >> logw;
    int b = r & 127;
    int t = r >> 7;
    if (t >= n_nodes[b]) buf[idx] = 0.0f;
}

// ---------------- SGEMM: C[M][N] = A[M][K] @ B[N][K]^T (+bias) ----------------
// 128x128 block tile, 8x8 microtile, K-panel 8, register prefetch.
// Requires M%128==0, N%128==0, K%8==0.
__global__ __launch_bounds__(256)
void sgemm2(const float* __restrict__ A, int lda,
            const float* __restrict__ B, int ldb,
            float* __restrict__ C, int ldc,
            const float* __restrict__ bias, int K)
{
    __shared__ float As[8 * 132];
    __shared__ float Bs[8 * 132];
    const int tid = threadIdx.x;
    const int m0 = blockIdx.y * 128;
    const int n0 = blockIdx.x * 128;
    const int arow = tid >> 1;          // 0..127
    const int ak   = (tid & 1) << 2;    // 0 or 4
    const int tx = tid & 15;
    const int ty = tid >> 4;

    const float* Ap = A + (long)(m0 + arow) * lda + ak;
    const float* Bp = B + (long)(n0 + arow) * ldb + ak;

    float acc[8][8];
    #pragma unroll
    for (int i = 0; i < 8; i++)
        #pragma unroll
        for (int j = 0; j < 8; j++) acc[i][j] = 0.0f;

    float4 pa = *(const float4*)Ap;
    float4 pb = *(const float4*)Bp;
    const int np = K >> 3;
    for (int p = 0; p < np; p++) {
        __syncthreads();
        As[(ak + 0) * 132 + arow] = pa.x;
        As[(ak + 1) * 132 + arow] = pa.y;
        As[(ak + 2) * 132 + arow] = pa.z;
        As[(ak + 3) * 132 + arow] = pa.w;
        Bs[(ak + 0) * 132 + arow] = pb.x;
        Bs[(ak + 1) * 132 + arow] = pb.y;
        Bs[(ak + 2) * 132 + arow] = pb.z;
        Bs[(ak + 3) * 132 + arow] = pb.w;
        __syncthreads();
        if (p + 1 < np) {
            pa = *(const float4*)(Ap + (p + 1) * 8);
            pb = *(const float4*)(Bp + (p + 1) * 8);
        }
        #pragma unroll
        for (int kk = 0; kk < 8; kk++) {
            float4 a0 = *(const float4*)&As[kk * 132 + (ty << 2)];
            float4 a1 = *(const float4*)&As[kk * 132 + 64 + (ty << 2)];
            float4 b0 = *(const float4*)&Bs[kk * 132 + (tx << 2)];
            float4 b1 = *(const float4*)&Bs[kk * 132 + 64 + (tx << 2)];
            float av[8] = {a0.x, a0.y, a0.z, a0.w, a1.x, a1.y, a1.z, a1.w};
            float bv[8] = {b0.x, b0.y, b0.z, b0.w, b1.x, b1.y, b1.z, b1.w};
            #pragma unroll
            for (int i = 0; i < 8; i++)
                #pragma unroll
                for (int j = 0; j < 8; j++)
                    acc[i][j] = fmaf(av[i], bv[j], acc[i][j]);
        }
    }

    #pragma unroll
    for (int i = 0; i < 8; i++) {
        int m = m0 + ((i < 4) ? ((ty << 2) + i) : (64 + (ty << 2) + i - 4));
        #pragma unroll
        for (int jh = 0; jh < 2; jh++) {
            int n = n0 + jh * 64 + (tx << 2);
            float4 v;
            v.x = acc[i][jh * 4 + 0] + (bias ? bias[n + 0] : 0.0f);
            v.y = acc[i][jh * 4 + 1] + (bias ? bias[n + 1] : 0.0f);
            v.z = acc[i][jh * 4 + 2] + (bias ? bias[n + 2] : 0.0f);
            v.w = acc[i][jh * 4 + 3] + (bias ? bias[n + 3] : 0.0f);
            *(float4*)&C[(long)m * ldc + n] = v;
        }
    }
}

// ---------------- persistent GRU layer ----------------
// Grid 128 = 16 j-tiles x 8 batch-tiles, 128 threads, 1 block/SM (smem-forced).
// Whh tile (3 x 32 x 512) resident in smem for all 64 steps (j-swizzled for
// conflict-free float2 reads). h exchanged through global via stcg/ldcg with a
// 16-block group barrier per step.
#define HS_FLOATS (16 * 520)
#define WS_FLOATS (3 * 512 * 32)
#define GRU_SMEM_BYTES ((HS_FLOATS + WS_FLOATS) * 4)   // 229888

__global__ __launch_bounds__(128, 1)
void gru_persist(const float* __restrict__ gi_all,   // [64][128][1536]
                 const float* __restrict__ Whh,      // [1536][512]
                 const float* __restrict__ bhh,      // [1536]
                 float* __restrict__ hs_out,         // [64][128][512]
                 float* __restrict__ hbuf0,
                 float* __restrict__ hbuf1)
{
    extern __shared__ float smem[];
    float* h_s = smem;                   // [16][520]
    float* w_s = smem + HS_FLOATS;       // swizzled [3][512][32]

    const int tid = threadIdx.x;
    const int jt = blockIdx.x & 15;
    const int bt = blockIdx.x >> 4;
    const int j0g = jt * 32;
    const int b0  = bt * 16;
    const int jp  = tid & 15;            // j-pair index (j = 2jp, 2jp+1)
    const int bo  = (tid >> 4) << 1;     // local batch offset (0,2,...,14)

    // one-time: load Whh tile into smem, transposed [g][k][j] with pair-swizzle
    for (int i = tid; i < WS_FLOATS; i += 128) {
        int k = i & 511;
        int row = i >> 9;                // 0..95
        int j = row & 31;
        int g = row >> 5;
        int addr = (g * 512 + k) * 32 + ((((j >> 1) ^ (k & 15)) << 1) | (j & 1));
        w_s[addr] = Whh[(g * 512 + j0g + j) * 512 + k];
    }
    // h_0 = 0
    for (int i = tid; i < HS_FLOATS; i += 128) h_s[i] = 0.0f;

    const int j0 = j0g + 2 * jp, j1 = j0 + 1;
    const float brj0 = bhh[j0],        brj1 = bhh[j1];
    const float bzj0 = bhh[512 + j0],  bzj1 = bhh[512 + j1];
    const float bnj0 = bhh[1024 + j0], bnj1 = bhh[1024 + j1];
    __syncthreads();

    const int swb = jp << 1;
    for (int t = 0; t < 64; t++) {
        ull aR0 = 0, aR1 = 0, aZ0 = 0, aZ1 = 0, aN0 = 0, aN1 = 0;
        const float* h0p = h_s + bo * 520;
        const float* h1p = h_s + (bo + 1) * 520;
        #pragma unroll 16
        for (int k = 0; k < 512; k++) {
            ull h20 = dup2(h0p[k]);
            ull h21 = dup2(h1p[k]);
            const float* wk = w_s + k * 32 + (swb ^ ((k & 15) << 1));
            ull w0 = *(const ull*)(wk);
            ull w1 = *(const ull*)(wk + 512 * 32);
            ull w2 = *(const ull*)(wk + 1024 * 32);
            aR0 = ffma2(w0, h20, aR0);  aR1 = ffma2(w0, h21, aR1);
            aZ0 = ffma2(w1, h20, aZ0);  aZ1 = ffma2(w1, h21, aZ1);
            aN0 = ffma2(w2, h20, aN0);  aN1 = ffma2(w2, h21, aN1);
        }

        float* wr = (t & 1) ? hbuf0 : hbuf1;
        // epilogue: 2 batches x 2 j per thread
        #pragma unroll
        for (int bi = 0; bi < 2; bi++) {
            int b = b0 + bo + bi;
            const float* grow = gi_all + ((long)t * BATCH + b) * G3;
            float r0l, r0h, z0l, z0h, n0l, n0h;
            unpack2(bi ? aR1 : aR0, r0l, r0h);
            unpack2(bi ? aZ1 : aZ0, z0l, z0h);
            unpack2(bi ? aN1 : aN0, n0l, n0h);

            float r = sigm(grow[j0] + r0l + brj0);
            float zg = sigm(grow[512 + j0] + z0l + bzj0);
            float nn = tanhf(grow[1024 + j0] + r * (n0l + bnj0));
            float hold = h_s[(bo + bi) * 520 + j0];
            float hnew = (1.0f - zg) * nn + zg * hold;
            __stcg(&wr[b * 512 + j0], hnew);
            hs_out[((long)t * BATCH + b) * 512 + j0] = hnew;

            r = sigm(grow[j1] + r0h + brj1);
            zg = sigm(grow[512 + j1] + z0h + bzj1);
            nn = tanhf(grow[1024 + j1] + r * (n0h + bnj1));
            hold = h_s[(bo + bi) * 520 + j1];
            hnew = (1.0f - zg) * nn + zg * hold;
            __stcg(&wr[b * 512 + j1], hnew);
            hs_out[((long)t * BATCH + b) * 512 + j1] = hnew;
        }

        if (t < 63) {
            __threadfence();
            __syncthreads();
            if (tid == 0) {
                atomicAdd(&g_ctr[bt], 1);
                int target = (t + 1) * 16;
                while (((volatile int*)g_ctr)[bt] < target) { }
                __threadfence();   // acquire: order h reloads after counter observation
            }
            __syncthreads();
            // reload full h for our 16 batches
            #pragma unroll
            for (int it = 0; it < 16; it++) {
                int f4 = tid + 128 * it;
                int bi = f4 >> 7;
                int k4 = (f4 & 127) << 2;
                float4 v = __ldcg((const float4*)(wr + (b0 + bi) * 512 + k4));
                float* dst = h_s + bi * 520 + k4;
                dst[0] = v.x; dst[1] = v.y; dst[2] = v.z; dst[3] = v.w;
            }
            __syncthreads();
        }
    }
}

// ---------------- pair kernel ----------------
__global__ __launch_bounds__(256)
void pair_kernel(const float* __restrict__ ca, const float* __restrict__ cb,
                 const float* __restrict__ b1, const float* __restrict__ W2,
                 const float* __restrict__ b2, const float* __restrict__ gu,
                 const int* __restrict__ n_nodes, float* __restrict__ out)
{
    int w    = (blockIdx.x * blockDim.x + threadIdx.x) >> 5;
    int lane = threadIdx.x & 31;
    int b = w / NPAIR;
    int p = w - b * NPAIR;
    int i = 0, rem = p, len = 63;
    while (rem >= len) { rem -= len; len--; i++; }
    int j = i + 1 + rem;

    const float* ra = ca + (long)(i * 128 + b) * HIDDEN;
    const float* rb = cb + (long)(j * 128 + b) * HIDDEN;
    float a0 = 0.0f, a1 = 0.0f;
    #pragma unroll
    for (int kk = 0; kk < 16; kk++) {
        int idx = (kk << 5) + lane;
        float v = ra[idx] + rb[idx] + b1[idx];
        v = fmaxf(v, 0.0f);
        a0 = fmaf(v, W2[idx], a0);
        a1 = fmaf(v, W2[HIDDEN + idx], a1);
    }
    #pragma unroll
    for (int off = 16; off; off >>= 1) {
        a0 += __shfl_down_sync(0xffffffffu, a0, off);
        a1 += __shfl_down_sync(0xffffffffu, a1, off);
    }
    if (lane == 0) {
        int n = n_nodes[b];
        if (i < n && j < n) {
            const float* g = gu + ((long)b * NPAIR + p) * 2;
            float g0 = -logf(-logf(g[0] + 1e-10f) + 1e-10f);
            float g1 = -logf(-logf(g[1] + 1e-10f) + 1e-10f);
            float s0 = a0 + b2[0] + g0;
            float s1 = a1 + b2[1] + g1;
            float val = (s0 >= s1) ? 1.0f : 0.0f;
            out[((long)b * 64 + i) * 64 + j] = val;
            out[((long)b * 64 + j) * 64 + i] = val;
        }
    }
}

// ---------------- launcher ----------------
extern "C" void kernel_launch(void* const* d_in, const int* in_sizes, int n_in,
                              void* d_out, int out_size)
{
    (void)in_sizes; (void)n_in;
    const float* z       = (const float*)d_in[0];
    const int*   n_nodes = (const int*)  d_in[1];
    const float* gu      = (const float*)d_in[3];
    const float* emb     = (const float*)d_in[4];
    const float* pe      = (const float*)d_in[5];
    const float* W_pre   = (const float*)d_in[6];
    const float* b_pre   = (const float*)d_in[7];
    const float* Wih0    = (const float*)d_in[8];
    const float* Whh0    = (const float*)d_in[9];
    const float* bih0    = (const float*)d_in[10];
    const float* bhh0    = (const float*)d_in[11];
    const float* Wih1    = (const float*)d_in[12];
    const float* Whh1    = (const float*)d_in[13];
    const float* bih1    = (const float*)d_in[14];
    const float* bhh1    = (const float*)d_in[15];
    const float* node_W  = (const float*)d_in[16];
    const float* adj_W1  = (const float*)d_in[17];
    const float* adj_b1  = (const float*)d_in[18];
    const float* adj_W2  = (const float*)d_in[19];
    const float* adj_b2  = (const float*)d_in[20];

    float *x, *seq, *gi, *hs0, *hs1, *node, *ca, *cb, *hbuf;
    int* ctr;
    cudaGetSymbolAddress((void**)&x,    g_x);
    cudaGetSymbolAddress((void**)&seq,  g_seq);
    cudaGetSymbolAddress((void**)&gi,   g_gi);
    cudaGetSymbolAddress((void**)&hs0,  g_hs0);
    cudaGetSymbolAddress((void**)&hs1,  g_hs1);
    cudaGetSymbolAddress((void**)&node, g_node);
    cudaGetSymbolAddress((void**)&ca,   g_ca);
    cudaGetSymbolAddress((void**)&cb,   g_cb);
    cudaGetSymbolAddress((void**)&hbuf, g_h);
    cudaGetSymbolAddress((void**)&ctr,  g_ctr);
    float* h0 = hbuf;
    float* h1 = hbuf + BATCH * HIDDEN;

    cudaFuncSetAttribute(gru_persist, cudaFuncAttributeMaxDynamicSharedMemorySize,
                         GRU_SMEM_BYTES);

    // 1) x = concat(z+pe, emb)
    build_x<<<SEQROWS * 512 / 256, 256>>>(z, pe, emb, x);
    // 2) seq = x @ W_pre^T + b_pre ; mask
    sgemm2<<<dim3(LATENT / 128, SEQROWS / 128), 256>>>(x, 512, W_pre, 512, seq, LATENT, b_pre, 512);
    mask_kernel<<<SEQROWS * LATENT / 256, 256>>>(seq, n_nodes, 8);
    // 3) gi0 = seq @ Wih0^T + bih0
    sgemm2<<<dim3(G3 / 128, SEQROWS / 128), 256>>>(seq, LATENT, Wih0, LATENT, gi, G3, bih0, LATENT);
    // 4) GRU layer 0 (persistent)
    cudaMemsetAsync(ctr, 0, 8 * sizeof(int));
    gru_persist<<<128, 128, GRU_SMEM_BYTES>>>(gi, Whh0, bhh0, hs0, h0, h1);
    // 5) gi1 = hs0 @ Wih1^T + bih1
    sgemm2<<<dim3(G3 / 128, SEQROWS / 128), 256>>>(hs0, HIDDEN, Wih1, HIDDEN, gi, G3, bih1, HIDDEN);
    // 6) GRU layer 1 (persistent)
    cudaMemsetAsync(ctr, 0, 8 * sizeof(int));
    gru_persist<<<128, 128, GRU_SMEM_BYTES>>>(gi, Whh1, bhh1, hs1, h0, h1);
    // 7) mask; node_emb = rnn_out @ node_W^T
    mask_kernel<<<SEQROWS * HIDDEN / 256, 256>>>(hs1, n_nodes, 9);
    sgemm2<<<dim3(HIDDEN / 128, SEQROWS / 128), 256>>>(hs1, HIDDEN, node_W, HIDDEN, node, HIDDEN, nullptr, HIDDEN);
    // 8) pair-MLP per-node halves
    sgemm2<<<dim3(HIDDEN / 128, SEQROWS / 128), 256>>>(node, HIDDEN, adj_W1, 1024, ca, HIDDEN, nullptr, HIDDEN);
    sgemm2<<<dim3(HIDDEN / 128, SEQROWS / 128), 256>>>(node, HIDDEN, adj_W1 + 512, 1024, cb, HIDDEN, nullptr, HIDDEN);
    // 9) adjacency
    cudaMemsetAsync(d_out, 0, (size_t)out_size * sizeof(float));
    pair_kernel<<<(BATCH * NPAIR * 32) / 256, 256>>>(ca, cb, adj_b1, adj_W2, adj_b2,
                                                     gu, n_nodes, (float*)d_out);
}

// round 10
// speedup vs baseline: 1.4410x; 1.1646x over previous
#include <cuda_runtime.h>
#include <math.h>

#define BATCH   128
#define M_NODES 64
#define SEQROWS (BATCH * M_NODES)   // 8192
#define LATENT  256
#define HIDDEN  512
#define G3      1536
#define NPAIR   2016

typedef unsigned long long ull;

// ---------------- scratch ----------------
__device__ float g_x   [SEQROWS * 512];
__device__ float g_seq [SEQROWS * LATENT];
__device__ float g_gi  [SEQROWS * G3];
__device__ float g_hs0 [SEQROWS * HIDDEN];
__device__ float g_hs1 [SEQROWS * HIDDEN];
__device__ float g_node[SEQROWS * HIDDEN];
__device__ float g_ca  [SEQROWS * HIDDEN];
__device__ float g_cb  [SEQROWS * HIDDEN];
__device__ float g_ht  [2][HIDDEN * BATCH];   // transposed h ping-pong: [k][b]
__device__ int   g_ctr [8];

// ---------------- helpers ----------------
__device__ __forceinline__ float sigm(float x) {
    return 0.5f * tanhf(0.5f * x) + 0.5f;
}
__device__ __forceinline__ ull ffma2(ull a, ull b, ull c) {
    ull d;
    asm("fma.rn.f32x2 %0, %1, %2, %3;" : "=l"(d) : "l"(a), "l"(b), "l"(c));
    return d;
}
__device__ __forceinline__ ull fadd2(ull a, ull b) {
    ull d;
    asm("add.rn.f32x2 %0, %1, %2;" : "=l"(d) : "l"(a), "l"(b));
    return d;
}
__device__ __forceinline__ ull dup2(float x) {
    ull r;
    asm("mov.b64 %0, {%1, %1};" : "=l"(r) : "f"(x));
    return r;
}
__device__ __forceinline__ void unpack2(ull v, float& lo, float& hi) {
    asm("mov.b64 {%0, %1}, %2;" : "=f"(lo), "=f"(hi) : "l"(v));
}

// ---------------- build x = concat(z+pe, emb), time-major rows ----------------
__global__ void build_x(const float* __restrict__ z, const float* __restrict__ pe,
                        const float* __restrict__ emb, float* __restrict__ x)
{
    int idx = blockIdx.x * blockDim.x + threadIdx.x;
    int c = idx & 511;
    int r = idx >> 9;
    int b = r & 127;
    int t = r >> 7;
    float v;
    if (c < 256) v = z[b * 256 + c] + pe[t * 256 + c];
    else         v = emb[t * 256 + (c - 256)];
    x[idx] = v;
}

// ---------------- masking ----------------
__global__ void mask_kernel(float* __restrict__ buf, const int* __restrict__ n_nodes,
                            int logw)
{
    int idx = blockIdx.x * blockDim.x + threadIdx.x;
    int r = idx >> logw;
    int b = r & 127;
    int t = r >> 7;
    if (t >= n_nodes[b]) buf[idx] = 0.0f;
}

// ---------------- SGEMM: C[M][N] = A[M][K] @ B[N][K]^T (+bias) ----------------
__global__ __launch_bounds__(256)
void sgemm2(const float* __restrict__ A, int lda,
            const float* __restrict__ B, int ldb,
            float* __restrict__ C, int ldc,
            const float* __restrict__ bias, int K)
{
    __shared__ float As[8 * 132];
    __shared__ float Bs[8 * 132];
    const int tid = threadIdx.x;
    const int m0 = blockIdx.y * 128;
    const int n0 = blockIdx.x * 128;
    const int arow = tid >> 1;
    const int ak   = (tid & 1) << 2;
    const int tx = tid & 15;
    const int ty = tid >> 4;

    const float* Ap = A + (long)(m0 + arow) * lda + ak;
    const float* Bp = B + (long)(n0 + arow) * ldb + ak;

    float acc[8][8];
    #pragma unroll
    for (int i = 0; i < 8; i++)
        #pragma unroll
        for (int j = 0; j < 8; j++) acc[i][j] = 0.0f;

    float4 pa = *(const float4*)Ap;
    float4 pb = *(const float4*)Bp;
    const int np = K >> 3;
    for (int p = 0; p < np; p++) {
        __syncthreads();
        As[(ak + 0) * 132 + arow] = pa.x;
        As[(ak + 1) * 132 + arow] = pa.y;
        As[(ak + 2) * 132 + arow] = pa.z;
        As[(ak + 3) * 132 + arow] = pa.w;
        Bs[(ak + 0) * 132 + arow] = pb.x;
        Bs[(ak + 1) * 132 + arow] = pb.y;
        Bs[(ak + 2) * 132 + arow] = pb.z;
        Bs[(ak + 3) * 132 + arow] = pb.w;
        __syncthreads();
        if (p + 1 < np) {
            pa = *(const float4*)(Ap + (p + 1) * 8);
            pb = *(const float4*)(Bp + (p + 1) * 8);
        }
        #pragma unroll
        for (int kk = 0; kk < 8; kk++) {
            float4 a0 = *(const float4*)&As[kk * 132 + (ty << 2)];
            float4 a1 = *(const float4*)&As[kk * 132 + 64 + (ty << 2)];
            float4 b0 = *(const float4*)&Bs[kk * 132 + (tx << 2)];
            float4 b1 = *(const float4*)&Bs[kk * 132 + 64 + (tx << 2)];
            float av[8] = {a0.x, a0.y, a0.z, a0.w, a1.x, a1.y, a1.z, a1.w};
            float bv[8] = {b0.x, b0.y, b0.z, b0.w, b1.x, b1.y, b1.z, b1.w};
            #pragma unroll
            for (int i = 0; i < 8; i++)
                #pragma unroll
                for (int j = 0; j < 8; j++)
                    acc[i][j] = fmaf(av[i], bv[j], acc[i][j]);
        }
    }

    #pragma unroll
    for (int i = 0; i < 8; i++) {
        int m = m0 + ((i < 4) ? ((ty << 2) + i) : (64 + (ty << 2) + i - 4));
        #pragma unroll
        for (int jh = 0; jh < 2; jh++) {
            int n = n0 + jh * 64 + (tx << 2);
            float4 v;
            v.x = acc[i][jh * 4 + 0] + (bias ? bias[n + 0] : 0.0f);
            v.y = acc[i][jh * 4 + 1] + (bias ? bias[n + 1] : 0.0f);
            v.z = acc[i][jh * 4 + 2] + (bias ? bias[n + 2] : 0.0f);
            v.w = acc[i][jh * 4 + 3] + (bias ? bias[n + 3] : 0.0f);
            *(float4*)&C[(long)m * ldc + n] = v;
        }
    }
}

// ---------------- persistent GRU, k-split warps ----------------
// Grid 128 = 16 jt (32 j) x 8 bt (16 b); 128 threads = 4 warps.
// Warp w covers k in [w*128, (w+1)*128) for the FULL 32j x 16b tile; lane = j.
// w_s[g][k][j ^ (k&31)] resident all 64 steps; h_s transposed [k][16 b].
// Cross-warp k-reduction through scratch overlaid on h_s (dead between steps).
#define WS2 (3 * 512 * 32)             // 196608 floats
#define HS2 (512 * 16)                 // 8192 floats
#define GRU_SMEM_BYTES ((WS2 + HS2) * 4)   // 229376

__global__ __launch_bounds__(128, 1)
void gru_persist2(const float* __restrict__ gi_all,   // [64][128][1536]
                  const float* __restrict__ Whh,      // [1536][512]
                  const float* __restrict__ bhh,      // [1536]
                  float* __restrict__ hs_out,         // [64][128][512]
                  float* __restrict__ hbt0,           // [512][128] transposed h
                  float* __restrict__ hbt1,
                  const int* __restrict__ n_nodes,
                  int mask_out)
{
    extern __shared__ float smem[];
    float* w_s = smem;                 // [3][512][32] swizzled
    float* h_s = smem + WS2;           // [512][16]

    const int tid  = threadIdx.x;
    const int lane = tid & 31;         // j within tile
    const int warp = tid >> 5;         // k-quarter / b-subset owner
    const int jt = blockIdx.x & 15;
    const int bt = blockIdx.x >> 4;
    const int j0g = jt * 32;
    const int b0  = bt * 16;

    // one-time: Whh -> smem, transposed [g][k][j] with XOR swizzle (conflict-free R/W)
    for (int i = tid; i < WS2; i += 128) {
        int k = i & 511;
        int row = i >> 9;              // 0..95
        int j = row & 31;
        int g = row >> 5;
        w_s[(g * 512 + k) * 32 + (j ^ (k & 31))] = Whh[(g * 512 + j0g + j) * 512 + k];
    }
    for (int i = tid; i < HS2; i += 128) h_s[i] = 0.0f;

    const int jg = j0g + lane;
    const float brj = bhh[jg], bzj = bhh[512 + jg], bnj = bhh[1024 + jg];
    int nb[4];
    #pragma unroll
    for (int bb = 0; bb < 4; bb++) nb[bb] = n_nodes[b0 + warp * 4 + bb];
    __syncthreads();

    const int k0 = warp * 128;
    const float* wp = w_s + k0 * 32;

    for (int t = 0; t < 64; t++) {
        // prefetch gi for my 4 batches (consumed ~6000 cyc later)
        float gir[4], giz[4], gin[4];
        #pragma unroll
        for (int bb = 0; bb < 4; bb++) {
            const float* grow = gi_all + ((long)t * BATCH + b0 + warp * 4 + bb) * G3 + jg;
            gir[bb] = grow[0];
            giz[bb] = grow[512];
            gin[bb] = grow[1024];
        }

        // ---- k-quarter matmul: 24 FFMA2 per k ----
        ull accR[8], accZ[8], accN[8];
        #pragma unroll
        for (int bp = 0; bp < 8; bp++) { accR[bp] = 0; accZ[bp] = 0; accN[bp] = 0; }

        #pragma unroll 4
        for (int kk = 0; kk < 128; kk++) {
            int sx = lane ^ (kk & 31);
            ull w0d = dup2(wp[kk * 32 + sx]);
            ull w1d = dup2(wp[512 * 32 + kk * 32 + sx]);
            ull w2d = dup2(wp[1024 * 32 + kk * 32 + sx]);
            const ull* hrow = (const ull*)(h_s + (k0 + kk) * 16);
            #pragma unroll
            for (int bp = 0; bp < 8; bp++) {
                ull h2 = hrow[bp];
                accR[bp] = ffma2(h2, w0d, accR[bp]);
                accZ[bp] = ffma2(h2, w1d, accZ[bp]);
                accN[bp] = ffma2(h2, w2d, accN[bp]);
            }
        }

        // capture h_old (hidden index jg) for my 4 batches before h_s is reused
        float hold[4];
        #pragma unroll
        for (int bb = 0; bb < 4; bb++) hold[bb] = h_s[jg * 16 + warp * 4 + bb];
        __syncthreads();

        // ---- cross-warp reduction through scratch (overlaid on h_s) ----
        ull* sc = (ull*)h_s;   // [warp][gate(3)][bp(8)][lane(32)] : 3072 ull = 24.5 KB
        #pragma unroll
        for (int bp = 0; bp < 8; bp++) {
            sc[(warp * 24 + bp) * 32 + lane]      = accR[bp];
            sc[(warp * 24 + 8 + bp) * 32 + lane]  = accZ[bp];
            sc[(warp * 24 + 16 + bp) * 32 + lane] = accN[bp];
        }
        __syncthreads();

        // warp w handles batches b0 + [w*4, w*4+4) => bpairs w*2, w*2+1
        ull sumR[2], sumZ[2], sumN[2];
        #pragma unroll
        for (int q = 0; q < 2; q++) {
            int bp = warp * 2 + q;
            ull r = sc[(0 * 24 + bp) * 32 + lane];
            ull z = sc[(0 * 24 + 8 + bp) * 32 + lane];
            ull n = sc[(0 * 24 + 16 + bp) * 32 + lane];
            #pragma unroll
            for (int w = 1; w < 4; w++) {
                r = fadd2(r, sc[(w * 24 + bp) * 32 + lane]);
                z = fadd2(z, sc[(w * 24 + 8 + bp) * 32 + lane]);
                n = fadd2(n, sc[(w * 24 + 16 + bp) * 32 + lane]);
            }
            sumR[q] = r; sumZ[q] = z; sumN[q] = n;
        }

        // ---- gates + h update ----
        float* wr = (t & 1) ? hbt0 : hbt1;
        #pragma unroll
        for (int q = 0; q < 2; q++) {
            float rl, rh, zl, zh, nl, nh;
            unpack2(sumR[q], rl, rh);
            unpack2(sumZ[q], zl, zh);
            unpack2(sumN[q], nl, nh);
            #pragma unroll
            for (int half = 0; half < 2; half++) {
                int bb = q * 2 + half;
                int b = b0 + warp * 4 + bb;
                float ghr = half ? rh : rl;
                float ghz = half ? zh : zl;
                float ghn = half ? nh : nl;
                float r  = sigm(gir[bb] + ghr + brj);
                float zg = sigm(giz[bb] + ghz + bzj);
                float nn = tanhf(gin[bb] + r * (ghn + bnj));
                float hnew = (1.0f - zg) * nn + zg * hold[bb];
                float outv = (mask_out && t >= nb[bb]) ? 0.0f : hnew;
                hs_out[((long)t * BATCH + b) * 512 + jg] = outv;
                __stcg(&wr[jg * BATCH + b], hnew);
            }
        }

        // ---- group barrier + h reload (transposed layout, no transpose needed) ----
        if (t < 63) {
            __threadfence();
            __syncthreads();
            if (tid == 0) {
                atomicAdd(&g_ctr[bt], 1);
                int target = (t + 1) * 16;
                while (((volatile int*)g_ctr)[bt] < target) { }
                __threadfence();
            }
            __syncthreads();
            #pragma unroll
            for (int it = 0; it < 16; it++) {
                int f = tid + 128 * it;        // 0..2047 float4
                int k = f >> 2;
                int b4 = (f & 3) << 2;
                float4 v = __ldcg((const float4*)(wr + k * BATCH + b0 + b4));
                *(float4*)&h_s[k * 16 + b4] = v;
            }
            __syncthreads();
        }
    }
}

// ---------------- pair kernel ----------------
__global__ __launch_bounds__(256)
void pair_kernel(const float* __restrict__ ca, const float* __restrict__ cb,
                 const float* __restrict__ b1, const float* __restrict__ W2,
                 const float* __restrict__ b2, const float* __restrict__ gu,
                 const int* __restrict__ n_nodes, float* __restrict__ out)
{
    int w    = (blockIdx.x * blockDim.x + threadIdx.x) >> 5;
    int lane = threadIdx.x & 31;
    int b = w / NPAIR;
    int p = w - b * NPAIR;
    int i = 0, rem = p, len = 63;
    while (rem >= len) { rem -= len; len--; i++; }
    int j = i + 1 + rem;

    const float* ra = ca + (long)(i * 128 + b) * HIDDEN;
    const float* rb = cb + (long)(j * 128 + b) * HIDDEN;
    float a0 = 0.0f, a1 = 0.0f;
    #pragma unroll
    for (int kk = 0; kk < 16; kk++) {
        int idx = (kk << 5) + lane;
        float v = ra[idx] + rb[idx] + b1[idx];
        v = fmaxf(v, 0.0f);
        a0 = fmaf(v, W2[idx], a0);
        a1 = fmaf(v, W2[HIDDEN + idx], a1);
    }
    #pragma unroll
    for (int off = 16; off; off >>= 1) {
        a0 += __shfl_down_sync(0xffffffffu, a0, off);
        a1 += __shfl_down_sync(0xffffffffu, a1, off);
    }
    if (lane == 0) {
        int n = n_nodes[b];
        if (i < n && j < n) {
            const float* g = gu + ((long)b * NPAIR + p) * 2;
            float g0 = -logf(-logf(g[0] + 1e-10f) + 1e-10f);
            float g1 = -logf(-logf(g[1] + 1e-10f) + 1e-10f);
            float s0 = a0 + b2[0] + g0;
            float s1 = a1 + b2[1] + g1;
            float val = (s0 >= s1) ? 1.0f : 0.0f;
            out[((long)b * 64 + i) * 64 + j] = val;
            out[((long)b * 64 + j) * 64 + i] = val;
        }
    }
}

// ---------------- launcher ----------------
extern "C" void kernel_launch(void* const* d_in, const int* in_sizes, int n_in,
                              void* d_out, int out_size)
{
    (void)in_sizes; (void)n_in;
    const float* z       = (const float*)d_in[0];
    const int*   n_nodes = (const int*)  d_in[1];
    const float* gu      = (const float*)d_in[3];
    const float* emb     = (const float*)d_in[4];
    const float* pe      = (const float*)d_in[5];
    const float* W_pre   = (const float*)d_in[6];
    const float* b_pre   = (const float*)d_in[7];
    const float* Wih0    = (const float*)d_in[8];
    const float* Whh0    = (const float*)d_in[9];
    const float* bih0    = (const float*)d_in[10];
    const float* bhh0    = (const float*)d_in[11];
    const float* Wih1    = (const float*)d_in[12];
    const float* Whh1    = (const float*)d_in[13];
    const float* bih1    = (const float*)d_in[14];
    const float* bhh1    = (const float*)d_in[15];
    const float* node_W  = (const float*)d_in[16];
    const float* adj_W1  = (const float*)d_in[17];
    const float* adj_b1  = (const float*)d_in[18];
    const float* adj_W2  = (const float*)d_in[19];
    const float* adj_b2  = (const float*)d_in[20];

    float *x, *seq, *gi, *hs0, *hs1, *node, *ca, *cb, *hbt;
    int* ctr;
    cudaGetSymbolAddress((void**)&x,    g_x);
    cudaGetSymbolAddress((void**)&seq,  g_seq);
    cudaGetSymbolAddress((void**)&gi,   g_gi);
    cudaGetSymbolAddress((void**)&hs0,  g_hs0);
    cudaGetSymbolAddress((void**)&hs1,  g_hs1);
    cudaGetSymbolAddress((void**)&node, g_node);
    cudaGetSymbolAddress((void**)&ca,   g_ca);
    cudaGetSymbolAddress((void**)&cb,   g_cb);
    cudaGetSymbolAddress((void**)&hbt,  g_ht);
    cudaGetSymbolAddress((void**)&ctr,  g_ctr);
    float* hbt0 = hbt;
    float* hbt1 = hbt + HIDDEN * BATCH;

    cudaFuncSetAttribute(gru_persist2, cudaFuncAttributeMaxDynamicSharedMemorySize,
                         GRU_SMEM_BYTES);

    // 1) x = concat(z+pe, emb)
    build_x<<<SEQROWS * 512 / 256, 256>>>(z, pe, emb, x);
    // 2) seq = x @ W_pre^T + b_pre ; mask
    sgemm2<<<dim3(LATENT / 128, SEQROWS / 128), 256>>>(x, 512, W_pre, 512, seq, LATENT, b_pre, 512);
    mask_kernel<<<SEQROWS * LATENT / 256, 256>>>(seq, n_nodes, 8);
    // 3) gi0 = seq @ Wih0^T + bih0
    sgemm2<<<dim3(G3 / 128, SEQROWS / 128), 256>>>(seq, LATENT, Wih0, LATENT, gi, G3, bih0, LATENT);
    // 4) GRU layer 0 (persistent, k-split)
    cudaMemsetAsync(ctr, 0, 8 * sizeof(int));
    gru_persist2<<<128, 128, GRU_SMEM_BYTES>>>(gi, Whh0, bhh0, hs0, hbt0, hbt1, n_nodes, 0);
    // 5) gi1 = hs0 @ Wih1^T + bih1
    sgemm2<<<dim3(G3 / 128, SEQROWS / 128), 256>>>(hs0, HIDDEN, Wih1, HIDDEN, gi, G3, bih1, HIDDEN);
    // 6) GRU layer 1 (persistent, k-split, mask fused into output)
    cudaMemsetAsync(ctr, 0, 8 * sizeof(int));
    gru_persist2<<<128, 128, GRU_SMEM_BYTES>>>(gi, Whh1, bhh1, hs1, hbt0, hbt1, n_nodes, 1);
    // 7) node_emb = rnn_out @ node_W^T  (hs1 already masked)
    sgemm2<<<dim3(HIDDEN / 128, SEQROWS / 128), 256>>>(hs1, HIDDEN, node_W, HIDDEN, node, HIDDEN, nullptr, HIDDEN);
    // 8) pair-MLP per-node halves
    sgemm2<<<dim3(HIDDEN / 128, SEQROWS / 128), 256>>>(node, HIDDEN, adj_W1, 1024, ca, HIDDEN, nullptr, HIDDEN);
    sgemm2<<<dim3(HIDDEN / 128, SEQROWS / 128), 256>>>(node, HIDDEN, adj_W1 + 512, 1024, cb, HIDDEN, nullptr, HIDDEN);
    // 9) adjacency
    cudaMemsetAsync(d_out, 0, (size_t)out_size * sizeof(float));
    pair_kernel<<<(BATCH * NPAIR * 32) / 256, 256>>>(ca, cb, adj_b1, adj_W2, adj_b2,
                                                     gu, n_nodes, (float*)d_out);
}